// round 14
// baseline (speedup 1.0000x reference)
#include <cuda_runtime.h>

// TransducerJoint: h[b,t,u,:] = f[b,t,:] + g[b,u,:] if t < f_len[b] && u < g_len[b] else 0
// B=16, T=256, U=96, H=512 (fp32). Output 805 MB -> pure HBM-write-bound.
// R14: champion structure (U_PER_BLK=2, 4KB span, 196608 CTAs, hoisted n_valid)
//      with st.global.wt (write-through) instead of .cs: no L2 dirty-line
//      allocation/writeback for the never-re-read output stream.

#define B_ 16
#define T_ 256
#define U_ 96
#define H_ 512
#define H4_ (H_ / 4)      // 128 float4 per H-row
#define U_PER_BLK 2

__device__ __forceinline__ void st_wt_v4(float4* p, const float4 v)
{
    asm volatile(
        "st.global.wt.v4.f32 [%0], {%1,%2,%3,%4};"
        :: "l"(p), "f"(v.x), "f"(v.y), "f"(v.z), "f"(v.w)
        : "memory");
}

__global__ __launch_bounds__(H4_, 16) void transducer_joint_kernel(
    const float4* __restrict__ f,      // (B, T, H/4)
    const float4* __restrict__ g,      // (B, U, H/4)
    const int*    __restrict__ f_len,  // (B,)
    const int*    __restrict__ g_len,  // (B,)
    float4*       __restrict__ out)    // (B, T, U, H/4)
{
    const int h4 = threadIdx.x;        // 0..127
    const int u0 = blockIdx.x * U_PER_BLK;
    const int t  = blockIdx.y;
    const int b  = blockIdx.z;

    // valid u count within [u0, u0+2), computed once
    int n_valid = 0;
    if (t < f_len[b]) {
        int r = g_len[b] - u0;
        n_valid = r < 0 ? 0 : (r > U_PER_BLK ? U_PER_BLK : r);
    }

    // f row chunk: loaded once, reused for both u's
    const float4 f4 = __ldg(f + ((size_t)b * T_ + t) * H4_ + h4);

    const float4* gbase = g + ((size_t)b * U_ + u0) * H4_ + h4;
    float4* obase = out + (((size_t)b * T_ + t) * U_ + u0) * H4_ + h4;

    const float4 zero = make_float4(0.f, 0.f, 0.f, 0.f);

#pragma unroll
    for (int du = 0; du < U_PER_BLK; ++du) {
        float4 r = zero;
        if (du < n_valid) {                       // single scalar predicate
            const float4 g4 = __ldg(gbase + (size_t)du * H4_);
            r.x = f4.x + g4.x;
            r.y = f4.y + g4.y;
            r.z = f4.z + g4.z;
            r.w = f4.w + g4.w;
        }
        st_wt_v4(obase + (size_t)du * H4_, r);    // write-through streaming store
    }
}

extern "C" void kernel_launch(void* const* d_in, const int* in_sizes, int n_in,
                              void* d_out, int out_size)
{
    const float4* f     = (const float4*)d_in[0];
    const float4* g     = (const float4*)d_in[1];
    const int*    f_len = (const int*)d_in[2];
    const int*    g_len = (const int*)d_in[3];
    float4*       out   = (float4*)d_out;

    dim3 grid(U_ / U_PER_BLK, T_, B_);   // (48, 256, 16) = 196608 CTAs
    dim3 block(H4_);                      // 128 threads
    transducer_joint_kernel<<<grid, block>>>(f, g, f_len, g_len, out);
}

// round 15
// speedup vs baseline: 1.2496x; 1.2496x over previous
#include <cuda_runtime.h>

// TransducerJoint: h[b,t,u,:] = f[b,t,:] + g[b,u,:] if t < f_len[b] && u < g_len[b] else 0
// B=16, T=256, U=96, H=512 (fp32). Output 805 MB -> pure HBM-write-bound.
//
// FINAL champion (R10/R12): U_PER_BLK=2 (4KB span/CTA, 196608 CTAs),
// 128 threads, warp-coherent full-row float4 __stcs streaming stores,
// hoisted n_valid, launch_bounds(128,16).
//
// Exhausted knobs: cache op (.cs >> default >> .wt), store width (128b > 256b),
// span {2,4,6,8,16,24,192}KB -> basin at 4-6KB, predicate form (tie),
// packing (full-row warps win). Steady-state ~7.4 TB/s write stream = ~92% of
// HBM3e spec; compute pipes <18%. Roofline reached.

#define B_ 16
#define T_ 256
#define U_ 96
#define H_ 512
#define H4_ (H_ / 4)      // 128 float4 per H-row
#define U_PER_BLK 2

__global__ __launch_bounds__(H4_, 16) void transducer_joint_kernel(
    const float4* __restrict__ f,      // (B, T, H/4)
    const float4* __restrict__ g,      // (B, U, H/4)
    const int*    __restrict__ f_len,  // (B,)
    const int*    __restrict__ g_len,  // (B,)
    float4*       __restrict__ out)    // (B, T, U, H/4)
{
    const int h4 = threadIdx.x;        // 0..127
    const int u0 = blockIdx.x * U_PER_BLK;
    const int t  = blockIdx.y;
    const int b  = blockIdx.z;

    // valid u count within [u0, u0+2), computed once
    int n_valid = 0;
    if (t < f_len[b]) {
        int r = g_len[b] - u0;
        n_valid = r < 0 ? 0 : (r > U_PER_BLK ? U_PER_BLK : r);
    }

    // f row chunk: loaded once, reused for both u's
    const float4 f4 = __ldg(f + ((size_t)b * T_ + t) * H4_ + h4);

    const float4* gbase = g + ((size_t)b * U_ + u0) * H4_ + h4;
    float4* obase = out + (((size_t)b * T_ + t) * U_ + u0) * H4_ + h4;

    const float4 zero = make_float4(0.f, 0.f, 0.f, 0.f);

#pragma unroll
    for (int du = 0; du < U_PER_BLK; ++du) {
        float4 r = zero;
        if (du < n_valid) {                       // single scalar predicate
            const float4 g4 = __ldg(gbase + (size_t)du * H4_);
            r.x = f4.x + g4.x;
            r.y = f4.y + g4.y;
            r.z = f4.z + g4.z;
            r.w = f4.w + g4.w;
        }
        __stcs(obase + (size_t)du * H4_, r);      // evict-first streaming store
    }
}

extern "C" void kernel_launch(void* const* d_in, const int* in_sizes, int n_in,
                              void* d_out, int out_size)
{
    const float4* f     = (const float4*)d_in[0];
    const float4* g     = (const float4*)d_in[1];
    const int*    f_len = (const int*)d_in[2];
    const int*    g_len = (const int*)d_in[3];
    float4*       out   = (float4*)d_out;

    dim3 grid(U_ / U_PER_BLK, T_, B_);   // (48, 256, 16) = 196608 CTAs
    dim3 block(H4_);                      // 128 threads
    transducer_joint_kernel<<<grid, block>>>(f, g, f_len, g_len, out);
}